// round 1
// baseline (speedup 1.0000x reference)
#include <cuda_runtime.h>
#include <math.h>

#define NB 32768
#define NK 64
#define ND 256

// ---------------- scratch (device globals: no allocation allowed) -------------
__device__ float g_q  [NB * 64];        // [B,64]   q = center @ Wq^T
__device__ float g_p  [NB * 512];       // [B,2,256] p[b,h] = q[b,h] @ Wk_h
__device__ float g_g1 [NB * 256];       // center part of gate pre-activation
__device__ float g_wn [NB * 512];       // [B,2,256] attention-weighted neighbor sum
__device__ float g_ctx[NB * 256];       // context

// =============================================================================
// Generic fp32 GEMM:  C[m,n] = sum_k A[m*lda+k] * W[n*ldw+k]      (K = 256)
// Tiles: BM=128, BN=64, BK=16; 256 threads; 8x4 per thread; reg-prefetched.
// FUSED=1: gated epilogue  out = g*center + (1-g)*ctx, g = sigmoid(acc+g1+bias)
// =============================================================================
template <int FUSED>
__global__ __launch_bounds__(256) void gemm_nt(
    const float* __restrict__ A, const float* __restrict__ W,
    float* __restrict__ C, int lda, int ldw, int ldc,
    const float* __restrict__ bias, const float* __restrict__ center,
    float* __restrict__ outp)
{
    __shared__ float As[16][132];
    __shared__ float Ws[16][68];

    const int tid = threadIdx.x;
    const int m0 = blockIdx.y * 128;
    const int n0 = blockIdx.x * 64;
    const int tm = tid >> 4;       // 0..15  -> rows tm*8 .. tm*8+7
    const int tn = tid & 15;       // 0..15  -> cols tn*4 .. tn*4+3

    const int ar = tid >> 2;       // 0..63 (A loader row; +64 for second)
    const int ac = tid & 3;        // k-quad
    const int wr = tid >> 2;       // 0..63 (W loader row)
    const int wc = tid & 3;

    float4 a0r, a1r, wvr;
    a0r = *(const float4*)(A + (size_t)(m0 + ar)      * lda + ac * 4);
    a1r = *(const float4*)(A + (size_t)(m0 + ar + 64) * lda + ac * 4);
    wvr = *(const float4*)(W + (size_t)(n0 + wr)      * ldw + wc * 4);

    float acc[8][4];
#pragma unroll
    for (int i = 0; i < 8; i++)
#pragma unroll
        for (int j = 0; j < 4; j++) acc[i][j] = 0.f;

#pragma unroll 1
    for (int kt = 0; kt < 16; kt++) {
        As[ac * 4 + 0][ar]      = a0r.x;
        As[ac * 4 + 1][ar]      = a0r.y;
        As[ac * 4 + 2][ar]      = a0r.z;
        As[ac * 4 + 3][ar]      = a0r.w;
        As[ac * 4 + 0][ar + 64] = a1r.x;
        As[ac * 4 + 1][ar + 64] = a1r.y;
        As[ac * 4 + 2][ar + 64] = a1r.z;
        As[ac * 4 + 3][ar + 64] = a1r.w;
        Ws[wc * 4 + 0][wr] = wvr.x;
        Ws[wc * 4 + 1][wr] = wvr.y;
        Ws[wc * 4 + 2][wr] = wvr.z;
        Ws[wc * 4 + 3][wr] = wvr.w;
        __syncthreads();

        if (kt < 15) {                       // prefetch next tile into registers
            const int k0 = (kt + 1) * 16;
            a0r = *(const float4*)(A + (size_t)(m0 + ar)      * lda + k0 + ac * 4);
            a1r = *(const float4*)(A + (size_t)(m0 + ar + 64) * lda + k0 + ac * 4);
            wvr = *(const float4*)(W + (size_t)(n0 + wr)      * ldw + k0 + wc * 4);
        }

#pragma unroll
        for (int k = 0; k < 16; k++) {
            const float4 a0 = *(const float4*)&As[k][tm * 8];
            const float4 a1 = *(const float4*)&As[k][tm * 8 + 4];
            const float4 wv = *(const float4*)&Ws[k][tn * 4];
            const float am[8] = {a0.x, a0.y, a0.z, a0.w, a1.x, a1.y, a1.z, a1.w};
            const float wm[4] = {wv.x, wv.y, wv.z, wv.w};
#pragma unroll
            for (int i = 0; i < 8; i++)
#pragma unroll
                for (int j = 0; j < 4; j++)
                    acc[i][j] = fmaf(am[i], wm[j], acc[i][j]);
        }
        __syncthreads();
    }

    const int nb = n0 + tn * 4;
#pragma unroll
    for (int i = 0; i < 8; i++) {
        const int m = m0 + tm * 8 + i;
        if (FUSED) {
            const float4 g1v = *(const float4*)(C      + (size_t)m * 256 + nb);
            const float4 bv  = *(const float4*)(bias   + nb);
            const float4 cv  = *(const float4*)(center + (size_t)m * 256 + nb);
            const float4 xv  = *(const float4*)(A      + (size_t)m * lda + nb);
            float4 o;
            float z, g;
            z = acc[i][0] + g1v.x + bv.x; g = 1.f / (1.f + expf(-z)); o.x = g * cv.x + (1.f - g) * xv.x;
            z = acc[i][1] + g1v.y + bv.y; g = 1.f / (1.f + expf(-z)); o.y = g * cv.y + (1.f - g) * xv.y;
            z = acc[i][2] + g1v.z + bv.z; g = 1.f / (1.f + expf(-z)); o.z = g * cv.z + (1.f - g) * xv.z;
            z = acc[i][3] + g1v.w + bv.w; g = 1.f / (1.f + expf(-z)); o.w = g * cv.w + (1.f - g) * xv.w;
            *(float4*)(outp + (size_t)m * 256 + nb) = o;
        } else {
            const float4 o = make_float4(acc[i][0], acc[i][1], acc[i][2], acc[i][3]);
            *(float4*)(C + (size_t)m * ldc + nb) = o;
        }
    }
}

// =============================================================================
// p kernel:  p[b,h,d] = sum_{a<32} q[b, h*32+a] * Wk[h*32+a, d]
// One CTA handles 64 consecutive b. Wk column d lives in 64 registers/thread.
// =============================================================================
__global__ __launch_bounds__(256) void p_kernel(const float* __restrict__ Wk)
{
    __shared__ float qs[64 * 64];
    const int t = threadIdx.x;              // t == d
    float wk[64];
#pragma unroll
    for (int r = 0; r < 64; r++) wk[r] = Wk[r * 256 + t];

    const int b0 = blockIdx.x * 64;
    const float4* qsrc = (const float4*)(g_q + (size_t)b0 * 64);
    for (int i = t; i < 1024; i += 256) ((float4*)qs)[i] = qsrc[i];
    __syncthreads();

#pragma unroll 1
    for (int bb = 0; bb < 64; bb++) {
        float p0 = 0.f, p1 = 0.f;
#pragma unroll
        for (int a4 = 0; a4 < 8; a4++) {
            const float4 q0 = *(const float4*)&qs[bb * 64 + a4 * 4];
            const float4 q1 = *(const float4*)&qs[bb * 64 + 32 + a4 * 4];
            p0 = fmaf(q0.x, wk[a4 * 4 + 0], p0);
            p0 = fmaf(q0.y, wk[a4 * 4 + 1], p0);
            p0 = fmaf(q0.z, wk[a4 * 4 + 2], p0);
            p0 = fmaf(q0.w, wk[a4 * 4 + 3], p0);
            p1 = fmaf(q1.x, wk[32 + a4 * 4 + 0], p1);
            p1 = fmaf(q1.y, wk[32 + a4 * 4 + 1], p1);
            p1 = fmaf(q1.z, wk[32 + a4 * 4 + 2], p1);
            p1 = fmaf(q1.w, wk[32 + a4 * 4 + 3], p1);
        }
        const size_t o = (size_t)(b0 + bb) * 512;
        g_p[o + t]       = p0;
        g_p[o + 256 + t] = p1;
    }
}

// =============================================================================
// Fused attention kernel: one CTA per b (256 threads).
//  - stage p[b] (512 f) + wts[b] (64 f) to smem
//  - stream neigh[b] (64x256 f) gmem->smem; compute both heads' score dots
//    in the same pass (thread t: row k=t>>2, quarter q4=t&3; shfl-reduce quad)
//  - softmax over K=64 (warps 0/1, one per head)
//  - weighted sum: thread t = column d; wn[b,h,d] = sum_k attn[h,k]*neigh[k,d]
// =============================================================================
#define SN_PAD 260   // row stride in floats (16B aligned, conflict-free column reads)

__global__ __launch_bounds__(256) void attn_kernel(
    const float* __restrict__ neigh, const float* __restrict__ wts)
{
    extern __shared__ float sm[];
    float* sN     = sm;                       // 64 * 260
    float* sP     = sm + 64 * SN_PAD;         // 512
    float* sWts   = sP + 512;                 // 64
    float* sScore = sWts + 64;                // 128
    float* sAttn  = sScore + 128;             // 128

    const int b = blockIdx.x;
    const int t = threadIdx.x;

    if (t < 128) ((float4*)sP)[t] = ((const float4*)(g_p + (size_t)b * 512))[t];
    if (t >= 128 && t < 192) sWts[t - 128] = wts[(size_t)b * 64 + (t - 128)];
    __syncthreads();

    const int k  = t >> 2;
    const int q4 = t & 3;
    const float4* src = (const float4*)(neigh + ((size_t)b * 64 + k) * 256 + q4 * 64);
    float4*       dst = (float4*)(sN + k * SN_PAD + q4 * 64);
    const float4* p0  = (const float4*)(sP + q4 * 64);
    const float4* p1  = (const float4*)(sP + 256 + q4 * 64);

    float s0 = 0.f, s1 = 0.f;
#pragma unroll 4
    for (int i = 0; i < 16; i++) {
        const float4 v = src[i];
        dst[i] = v;
        const float4 a = p0[i];
        const float4 c = p1[i];
        s0 += v.x * a.x + v.y * a.y + v.z * a.z + v.w * a.w;
        s1 += v.x * c.x + v.y * c.y + v.z * c.z + v.w * c.w;
    }
    s0 += __shfl_xor_sync(0xffffffffu, s0, 1);
    s0 += __shfl_xor_sync(0xffffffffu, s0, 2);
    s1 += __shfl_xor_sync(0xffffffffu, s1, 1);
    s1 += __shfl_xor_sync(0xffffffffu, s1, 2);
    if (q4 == 0) {
        const float w = sWts[k] * 0.17677669529663687f;   // 1/sqrt(32)
        sScore[k]      = s0 * w;
        sScore[64 + k] = s1 * w;
    }
    __syncthreads();

    if (t < 64) {                       // warps 0,1 fully active: full-mask shfl ok
        const int h = t >> 5, lane = t & 31;
        const float sa = sScore[h * 64 + lane];
        const float sb = sScore[h * 64 + 32 + lane];
        float mx = fmaxf(sa, sb);
#pragma unroll
        for (int o = 16; o; o >>= 1) mx = fmaxf(mx, __shfl_xor_sync(0xffffffffu, mx, o));
        const float ea = expf(sa - mx), eb = expf(sb - mx);
        float sum = ea + eb;
#pragma unroll
        for (int o = 16; o; o >>= 1) sum += __shfl_xor_sync(0xffffffffu, sum, o);
        const float inv = 1.f / sum;
        sAttn[h * 64 + lane]      = ea * inv;
        sAttn[h * 64 + 32 + lane] = eb * inv;
    }
    __syncthreads();

    float acc0 = 0.f, acc1 = 0.f;
#pragma unroll
    for (int kk = 0; kk < 64; kk += 4) {
        const float4 a0 = *(const float4*)&sAttn[kk];
        const float4 a1 = *(const float4*)&sAttn[64 + kk];
        const float v0 = sN[(kk + 0) * SN_PAD + t];
        const float v1 = sN[(kk + 1) * SN_PAD + t];
        const float v2 = sN[(kk + 2) * SN_PAD + t];
        const float v3 = sN[(kk + 3) * SN_PAD + t];
        acc0 += a0.x * v0 + a0.y * v1 + a0.z * v2 + a0.w * v3;
        acc1 += a1.x * v0 + a1.y * v1 + a1.z * v2 + a1.w * v3;
    }
    const size_t o = (size_t)b * 512;
    g_wn[o + t]       = acc0;
    g_wn[o + 256 + t] = acc1;
}

#define ATTN_SMEM ((64 * SN_PAD + 512 + 64 + 128 + 128) * 4)

// =============================================================================
extern "C" void kernel_launch(void* const* d_in, const int* in_sizes, int n_in,
                              void* d_out, int out_size)
{
    const float* center = (const float*)d_in[0];
    const float* neigh  = (const float*)d_in[1];
    const float* wts    = (const float*)d_in[2];
    const float* Wq     = (const float*)d_in[3];
    const float* Wk     = (const float*)d_in[4];
    const float* Wv     = (const float*)d_in[5];
    const float* Wg     = (const float*)d_in[6];
    const float* bg     = (const float*)d_in[7];
    float* out = (float*)d_out;

    float *q_, *g1_, *wn_, *ctx_;
    cudaGetSymbolAddress((void**)&q_,   g_q);
    cudaGetSymbolAddress((void**)&g1_,  g_g1);
    cudaGetSymbolAddress((void**)&wn_,  g_wn);
    cudaGetSymbolAddress((void**)&ctx_, g_ctx);

    cudaFuncSetAttribute(attn_kernel,
                         cudaFuncAttributeMaxDynamicSharedMemorySize, ATTN_SMEM);

    const dim3 blk(256);

    // q = center @ Wq^T                      [B,64]
    gemm_nt<0><<<dim3(1, 256), blk>>>(center, Wq, q_, 256, 256, 64,
                                      nullptr, nullptr, nullptr);
    // g1 = center @ W_gate[:, :256]^T        [B,256]
    gemm_nt<0><<<dim3(4, 256), blk>>>(center, Wg, g1_, 256, 512, 256,
                                      nullptr, nullptr, nullptr);
    // p[b,h] = q[b,h] @ Wk_h                 [B,2,256]
    p_kernel<<<512, blk>>>(Wk);
    // attention -> wn                        [B,2,256]
    attn_kernel<<<NB, blk, ATTN_SMEM>>>(neigh, wts);
    // context_h = wn_h @ Wv_h^T              [B,256] (block-diagonal over heads)
    gemm_nt<0><<<dim3(2, 256), blk>>>(wn_,       Wv,            ctx_,       512, 256, 256,
                                      nullptr, nullptr, nullptr);
    gemm_nt<0><<<dim3(2, 256), blk>>>(wn_ + 256, Wv + 128 * 256, ctx_ + 128, 512, 256, 256,
                                      nullptr, nullptr, nullptr);
    // g2 = ctx @ W_gate[:, 256:]^T, fused gate epilogue -> out
    gemm_nt<1><<<dim3(4, 256), blk>>>(ctx_, Wg + 256, g1_, 256, 512, 256,
                                      bg, center, out);
}

// round 3
// speedup vs baseline: 1.9389x; 1.9389x over previous
#include <cuda_runtime.h>
#include <math.h>
#include <stdint.h>

#define NB 32768

// ---------------- scratch (device globals: no allocation allowed) -------------
__device__ float g_q  [NB * 64];        // [B,64]   q = center @ Wq^T
__device__ float g_p  [NB * 512];       // [B,2,256] p[b,h] = q[b,h] @ Wk_h
__device__ float g_g1 [NB * 256];       // center part of gate pre-activation
__device__ float g_wn [NB * 512];       // [B,2,256] attention-weighted neighbor sum
__device__ float g_ctx[NB * 256];       // context

// =============================================================================
// tf32 helpers (legacy mma.sync path — compute_103 baseline, no 'a' features)
// =============================================================================
__device__ __forceinline__ uint32_t f2tf(float x) {
    uint32_t r;
    asm("cvt.rna.tf32.f32 %0, %1;" : "=r"(r) : "f"(x));
    return r;
}

__device__ __forceinline__ void mma_tf32(float* d, const uint32_t* a, const uint32_t* b) {
    asm volatile(
        "mma.sync.aligned.m16n8k8.row.col.f32.tf32.tf32.f32 "
        "{%0,%1,%2,%3}, {%4,%5,%6,%7}, {%8,%9}, {%0,%1,%2,%3};"
        : "+f"(d[0]), "+f"(d[1]), "+f"(d[2]), "+f"(d[3])
        : "r"(a[0]), "r"(a[1]), "r"(a[2]), "r"(a[3]), "r"(b[0]), "r"(b[1]));
}

// =============================================================================
// Tensor-core GEMM (mma.sync tf32):  C[m,n] = sum_k A[m,k] * W[n,k]   K=256
// CTA tile: BM=128, BN=64, BK=32. 256 threads = 8 warps as 4(m) x 2(n):
// warp tile 32x32 = 2 m-atoms x 4 n-atoms of m16n8k8.
// Smem k-major: As[k][128] stride 132, Ws[k][64] stride 68 (frag reads
// hit banks 4c+r -> conflict-free). Double buffered, 1 sync/iter.
// EPI=1: gated epilogue out = g*center + (1-g)*A, g = sigmoid(acc + C + bias)
// =============================================================================
#define AS_STR 132
#define WS_STR 68
#define AS_FLOATS (32 * AS_STR)      // 4224
#define WS_FLOATS (32 * WS_STR)      // 2176
#define GEMM_SMEM_BYTES ((2 * AS_FLOATS + 2 * WS_FLOATS) * 4)   // 51200

template <int EPI>
__global__ __launch_bounds__(256) void gemm_mma(
    const float* __restrict__ A, const float* __restrict__ W,
    float* __restrict__ C, int lda, int ldw, int ldc,
    const float* __restrict__ bias, const float* __restrict__ center,
    float* __restrict__ outp)
{
    extern __shared__ float ds[];
    float* Asb[2] = {ds, ds + AS_FLOATS};
    float* Wsb[2] = {ds + 2 * AS_FLOATS, ds + 2 * AS_FLOATS + WS_FLOATS};

    const int tid  = threadIdx.x;
    const int wid  = tid >> 5;
    const int lane = tid & 31;
    const int m0   = blockIdx.x * 128;
    const int n0   = blockIdx.y * 64;
    const int wm   = (wid & 3) * 32;       // warp row offset in tile
    const int wn   = (wid >> 2) * 32;      // warp col offset in tile

    // loader coordinates
    const int arow = tid >> 1;                   // 0..127 (2 float4 per row? no:)
    // A tile: 128 rows x 8 float4 = 1024; thread does 4: idx = tid + 256*i
    // W tile: 64 rows x 8 float4 = 512;   thread does 2

    float4 ra[4], rw[2];
    {
        const float* Ab = A + (size_t)m0 * lda;
        const float* Wb = W + (size_t)n0 * ldw;
#pragma unroll
        for (int i = 0; i < 4; i++) {
            const int idx = tid + 256 * i, r = idx >> 3, kq = idx & 7;
            ra[i] = *(const float4*)(Ab + (size_t)r * lda + kq * 4);
        }
#pragma unroll
        for (int i = 0; i < 2; i++) {
            const int idx = tid + 256 * i, r = idx >> 3, kq = idx & 7;
            rw[i] = *(const float4*)(Wb + (size_t)r * ldw + kq * 4);
        }
    }

    float acc[2][4][4];
#pragma unroll
    for (int i = 0; i < 2; i++)
#pragma unroll
        for (int j = 0; j < 4; j++)
#pragma unroll
            for (int v = 0; v < 4; v++) acc[i][j][v] = 0.f;

    // store chunk 0 into buffer 0
    {
        float* As = Asb[0];
        float* Ws = Wsb[0];
#pragma unroll
        for (int i = 0; i < 4; i++) {
            const int idx = tid + 256 * i, r = idx >> 3, kq = idx & 7;
            As[(kq * 4 + 0) * AS_STR + r] = __uint_as_float(f2tf(ra[i].x));
            As[(kq * 4 + 1) * AS_STR + r] = __uint_as_float(f2tf(ra[i].y));
            As[(kq * 4 + 2) * AS_STR + r] = __uint_as_float(f2tf(ra[i].z));
            As[(kq * 4 + 3) * AS_STR + r] = __uint_as_float(f2tf(ra[i].w));
        }
#pragma unroll
        for (int i = 0; i < 2; i++) {
            const int idx = tid + 256 * i, r = idx >> 3, kq = idx & 7;
            Ws[(kq * 4 + 0) * WS_STR + r] = __uint_as_float(f2tf(rw[i].x));
            Ws[(kq * 4 + 1) * WS_STR + r] = __uint_as_float(f2tf(rw[i].y));
            Ws[(kq * 4 + 2) * WS_STR + r] = __uint_as_float(f2tf(rw[i].z));
            Ws[(kq * 4 + 3) * WS_STR + r] = __uint_as_float(f2tf(rw[i].w));
        }
    }
    __syncthreads();

#pragma unroll 1
    for (int it = 0; it < 8; it++) {
        const int cur = it & 1;
        // prefetch next chunk gmem->regs
        if (it < 7) {
            const int kb = (it + 1) * 32;
            const float* Ab = A + (size_t)m0 * lda + kb;
            const float* Wb = W + (size_t)n0 * ldw + kb;
#pragma unroll
            for (int i = 0; i < 4; i++) {
                const int idx = tid + 256 * i, r = idx >> 3, kq = idx & 7;
                ra[i] = *(const float4*)(Ab + (size_t)r * lda + kq * 4);
            }
#pragma unroll
            for (int i = 0; i < 2; i++) {
                const int idx = tid + 256 * i, r = idx >> 3, kq = idx & 7;
                rw[i] = *(const float4*)(Wb + (size_t)r * ldw + kq * 4);
            }
        }
        // compute current buffer: 4 k8-steps
        {
            const float* As = Asb[cur];
            const float* Ws = Wsb[cur];
#pragma unroll
            for (int ks = 0; ks < 4; ks++) {
                const int kk = ks * 8;
                uint32_t afr[2][4], bfr[4][2];
                const int c = lane & 3, r = lane >> 2;
#pragma unroll
                for (int i = 0; i < 2; i++) {
                    const int r0 = wm + i * 16 + r;
                    afr[i][0] = __float_as_uint(As[(kk + c) * AS_STR + r0]);
                    afr[i][1] = __float_as_uint(As[(kk + c) * AS_STR + r0 + 8]);
                    afr[i][2] = __float_as_uint(As[(kk + c + 4) * AS_STR + r0]);
                    afr[i][3] = __float_as_uint(As[(kk + c + 4) * AS_STR + r0 + 8]);
                }
#pragma unroll
                for (int j = 0; j < 4; j++) {
                    const int c0 = wn + j * 8 + r;
                    bfr[j][0] = __float_as_uint(Ws[(kk + c) * WS_STR + c0]);
                    bfr[j][1] = __float_as_uint(Ws[(kk + c + 4) * WS_STR + c0]);
                }
#pragma unroll
                for (int i = 0; i < 2; i++)
#pragma unroll
                    for (int j = 0; j < 4; j++)
                        mma_tf32(acc[i][j], afr[i], bfr[j]);
            }
        }
        // store prefetched into other buffer
        if (it < 7) {
            const int nxt = 1 - cur;
            float* As = Asb[nxt];
            float* Ws = Wsb[nxt];
#pragma unroll
            for (int i = 0; i < 4; i++) {
                const int idx = tid + 256 * i, r = idx >> 3, kq = idx & 7;
                As[(kq * 4 + 0) * AS_STR + r] = __uint_as_float(f2tf(ra[i].x));
                As[(kq * 4 + 1) * AS_STR + r] = __uint_as_float(f2tf(ra[i].y));
                As[(kq * 4 + 2) * AS_STR + r] = __uint_as_float(f2tf(ra[i].z));
                As[(kq * 4 + 3) * AS_STR + r] = __uint_as_float(f2tf(ra[i].w));
            }
#pragma unroll
            for (int i = 0; i < 2; i++) {
                const int idx = tid + 256 * i, r = idx >> 3, kq = idx & 7;
                Ws[(kq * 4 + 0) * WS_STR + r] = __uint_as_float(f2tf(rw[i].x));
                Ws[(kq * 4 + 1) * WS_STR + r] = __uint_as_float(f2tf(rw[i].y));
                Ws[(kq * 4 + 2) * WS_STR + r] = __uint_as_float(f2tf(rw[i].z));
                Ws[(kq * 4 + 3) * WS_STR + r] = __uint_as_float(f2tf(rw[i].w));
            }
        }
        __syncthreads();
    }

    // ---------------- epilogue -----------------------------------------------
    const int r = lane >> 2, c2 = (lane & 3) * 2;
#pragma unroll
    for (int i = 0; i < 2; i++) {
#pragma unroll
        for (int j = 0; j < 4; j++) {
            const int row0 = m0 + wm + i * 16 + r;
            const int col  = n0 + wn + j * 8 + c2;
#pragma unroll
            for (int half = 0; half < 2; half++) {
                const int row = row0 + half * 8;
                const float d0 = acc[i][j][2 * half + 0];
                const float d1 = acc[i][j][2 * half + 1];
                if (EPI == 0) {
                    *(float2*)(C + (size_t)row * ldc + col) = make_float2(d0, d1);
                } else {
                    const float2 g1v = *(const float2*)(C      + (size_t)row * 256 + col);
                    const float2 bv  = *(const float2*)(bias   + col);
                    const float2 cv  = *(const float2*)(center + (size_t)row * 256 + col);
                    const float2 xv  = *(const float2*)(A      + (size_t)row * lda + col);
                    float z0 = d0 + g1v.x + bv.x;
                    float z1 = d1 + g1v.y + bv.y;
                    const float gg0 = 1.f / (1.f + __expf(-z0));
                    const float gg1 = 1.f / (1.f + __expf(-z1));
                    float2 o;
                    o.x = gg0 * cv.x + (1.f - gg0) * xv.x;
                    o.y = gg1 * cv.y + (1.f - gg1) * xv.y;
                    *(float2*)(outp + (size_t)row * 256 + col) = o;
                }
            }
        }
    }
}

// =============================================================================
// p kernel:  p[b,h,d] = sum_{a<32} q[b, h*32+a] * Wk[h*32+a, d]
// =============================================================================
__global__ __launch_bounds__(256) void p_kernel(const float* __restrict__ Wk)
{
    __shared__ float qs[64 * 64];
    const int t = threadIdx.x;              // t == d
    float wk[64];
#pragma unroll
    for (int r = 0; r < 64; r++) wk[r] = Wk[r * 256 + t];

    const int b0 = blockIdx.x * 64;
    const float4* qsrc = (const float4*)(g_q + (size_t)b0 * 64);
    for (int i = t; i < 1024; i += 256) ((float4*)qs)[i] = qsrc[i];
    __syncthreads();

#pragma unroll 1
    for (int bb = 0; bb < 64; bb++) {
        float p0 = 0.f, p1 = 0.f;
#pragma unroll
        for (int a4 = 0; a4 < 8; a4++) {
            const float4 q0 = *(const float4*)&qs[bb * 64 + a4 * 4];
            const float4 q1 = *(const float4*)&qs[bb * 64 + 32 + a4 * 4];
            p0 = fmaf(q0.x, wk[a4 * 4 + 0], p0);
            p0 = fmaf(q0.y, wk[a4 * 4 + 1], p0);
            p0 = fmaf(q0.z, wk[a4 * 4 + 2], p0);
            p0 = fmaf(q0.w, wk[a4 * 4 + 3], p0);
            p1 = fmaf(q1.x, wk[32 + a4 * 4 + 0], p1);
            p1 = fmaf(q1.y, wk[32 + a4 * 4 + 1], p1);
            p1 = fmaf(q1.z, wk[32 + a4 * 4 + 2], p1);
            p1 = fmaf(q1.w, wk[32 + a4 * 4 + 3], p1);
        }
        const size_t o = (size_t)(b0 + bb) * 512;
        g_p[o + t]       = p0;
        g_p[o + 256 + t] = p1;
    }
}

// =============================================================================
// Flash-style attention: one CTA per b, 256 threads = 8 warps.
// Warp w handles neighbor k = it*8 + w per chunk; lane owns dims 4*lane (lo)
// and 128+4*lane (hi) per head. Online softmax: stats lanes (warp 0, lanes
// 0..15; h = lane>>3, k8 = lane&7) keep running (m,l); per-chunk weights and
// rescale broadcast via smem. Per-warp partial context accumulators in regs,
// cross-warp reduced through 16KB smem at the end. neigh read EXACTLY once.
// =============================================================================
__global__ __launch_bounds__(256) void attn_flash(
    const float* __restrict__ neigh, const float* __restrict__ wts)
{
    __shared__ float sAcc[8][512];
    __shared__ float sScore[2][8];
    __shared__ float sW[2][8];
    __shared__ float sR[2];
    __shared__ float sL[2];
    __shared__ float sWt[64];

    const int b    = blockIdx.x;
    const int t    = threadIdx.x;
    const int w    = t >> 5;       // warp id = k-slot
    const int lane = t & 31;

    if (t < 64) sWt[t] = wts[(size_t)b * 64 + t] * 0.17677669529663687f; // /sqrt(32)

    const float4* pp = (const float4*)(g_p + (size_t)b * 512);
    const float4 p0a = pp[lane];       // head0 dims 4*lane..
    const float4 p0b = pp[32 + lane];  // head0 dims 128+4*lane..
    const float4 p1a = pp[64 + lane];
    const float4 p1b = pp[96 + lane];

    float4 a0a = {0, 0, 0, 0}, a0b = {0, 0, 0, 0};
    float4 a1a = {0, 0, 0, 0}, a1b = {0, 0, 0, 0};
    float m_run = -1e30f, l_run = 0.f;   // live only on stats lanes

    const float* nb = neigh + (size_t)b * 64 * 256;

#pragma unroll 1
    for (int it = 0; it < 8; it++) {
        const int k = it * 8 + w;
        const float4 va = *(const float4*)(nb + k * 256 + 4 * lane);
        const float4 vb = *(const float4*)(nb + k * 256 + 128 + 4 * lane);

        float s0 = va.x * p0a.x + va.y * p0a.y + va.z * p0a.z + va.w * p0a.w
                 + vb.x * p0b.x + vb.y * p0b.y + vb.z * p0b.z + vb.w * p0b.w;
        float s1 = va.x * p1a.x + va.y * p1a.y + va.z * p1a.z + va.w * p1a.w
                 + vb.x * p1b.x + vb.y * p1b.y + vb.z * p1b.z + vb.w * p1b.w;
#pragma unroll
        for (int o = 16; o; o >>= 1) {
            s0 += __shfl_xor_sync(0xffffffffu, s0, o);
            s1 += __shfl_xor_sync(0xffffffffu, s1, o);
        }
        if (lane == 0) { sScore[0][w] = s0; sScore[1][w] = s1; }
        __syncthreads();

        if (w == 0 && lane < 16) {
            const int h = lane >> 3, k8 = lane & 7;
            const float s = sScore[h][k8] * sWt[it * 8 + k8];
            float gmx = s;
#pragma unroll
            for (int o = 1; o < 8; o <<= 1)
                gmx = fmaxf(gmx, __shfl_xor_sync(0x0000ffffu, gmx, o));
            const float mnew = fmaxf(m_run, gmx);
            const float rsc  = __expf(m_run - mnew);
            const float wgt  = __expf(s - mnew);
            float lsum = wgt;
#pragma unroll
            for (int o = 1; o < 8; o <<= 1)
                lsum += __shfl_xor_sync(0x0000ffffu, lsum, o);
            l_run = l_run * rsc + lsum;
            m_run = mnew;
            sW[h][k8] = wgt;
            if (k8 == 0) sR[h] = rsc;
            if (it == 7 && k8 == 0) sL[h] = l_run;
        }
        __syncthreads();

        const float r0 = sR[0], r1 = sR[1];
        const float w0 = sW[0][w], w1 = sW[1][w];
        a0a.x = a0a.x * r0 + w0 * va.x;  a0a.y = a0a.y * r0 + w0 * va.y;
        a0a.z = a0a.z * r0 + w0 * va.z;  a0a.w = a0a.w * r0 + w0 * va.w;
        a0b.x = a0b.x * r0 + w0 * vb.x;  a0b.y = a0b.y * r0 + w0 * vb.y;
        a0b.z = a0b.z * r0 + w0 * vb.z;  a0b.w = a0b.w * r0 + w0 * vb.w;
        a1a.x = a1a.x * r1 + w1 * va.x;  a1a.y = a1a.y * r1 + w1 * va.y;
        a1a.z = a1a.z * r1 + w1 * va.z;  a1a.w = a1a.w * r1 + w1 * va.w;
        a1b.x = a1b.x * r1 + w1 * vb.x;  a1b.y = a1b.y * r1 + w1 * vb.y;
        a1b.z = a1b.z * r1 + w1 * vb.z;  a1b.w = a1b.w * r1 + w1 * vb.w;
    }

    // cross-warp reduction of partial contexts
    float4* row = (float4*)&sAcc[w][0];
    row[lane]      = a0a;      // head0 dims 4*lane
    row[32 + lane] = a0b;      // head0 dims 128+4*lane
    row[64 + lane] = a1a;
    row[96 + lane] = a1b;
    __syncthreads();

    const float inv0 = 1.f / sL[0];
    const float inv1 = 1.f / sL[1];
    float s_lo = 0.f, s_hi = 0.f;
#pragma unroll
    for (int ww = 0; ww < 8; ww++) {
        s_lo += sAcc[ww][t];
        s_hi += sAcc[ww][t + 256];
    }
    g_wn[(size_t)b * 512 + t]       = s_lo * inv0;
    g_wn[(size_t)b * 512 + 256 + t] = s_hi * inv1;
}

// =============================================================================
extern "C" void kernel_launch(void* const* d_in, const int* in_sizes, int n_in,
                              void* d_out, int out_size)
{
    const float* center = (const float*)d_in[0];
    const float* neigh  = (const float*)d_in[1];
    const float* wts    = (const float*)d_in[2];
    const float* Wq     = (const float*)d_in[3];
    const float* Wk     = (const float*)d_in[4];
    const float* Wv     = (const float*)d_in[5];
    const float* Wg     = (const float*)d_in[6];
    const float* bg     = (const float*)d_in[7];
    float* out = (float*)d_out;

    float *q_, *g1_, *wn_, *ctx_;
    cudaGetSymbolAddress((void**)&q_,   g_q);
    cudaGetSymbolAddress((void**)&g1_,  g_g1);
    cudaGetSymbolAddress((void**)&wn_,  g_wn);
    cudaGetSymbolAddress((void**)&ctx_, g_ctx);

    cudaFuncSetAttribute(gemm_mma<0>,
                         cudaFuncAttributeMaxDynamicSharedMemorySize, GEMM_SMEM_BYTES);
    cudaFuncSetAttribute(gemm_mma<1>,
                         cudaFuncAttributeMaxDynamicSharedMemorySize, GEMM_SMEM_BYTES);

    const dim3 blk(256);

    // q = center @ Wq^T                       [B,64]
    gemm_mma<0><<<dim3(256, 1), blk, GEMM_SMEM_BYTES>>>(
        center, Wq, q_, 256, 256, 64, nullptr, nullptr, nullptr);
    // g1 = center @ W_gate[:, :256]^T         [B,256]
    gemm_mma<0><<<dim3(256, 4), blk, GEMM_SMEM_BYTES>>>(
        center, Wg, g1_, 256, 512, 256, nullptr, nullptr, nullptr);
    // p[b,h] = q[b,h] @ Wk_h                  [B,2,256]
    p_kernel<<<512, blk>>>(Wk);
    // attention -> wn                         [B,2,256]
    attn_flash<<<NB, blk>>>(neigh, wts);
    // context_h = wn_h @ Wv_h^T               [B,256] (block-diagonal over heads)
    gemm_mma<0><<<dim3(256, 2), blk, GEMM_SMEM_BYTES>>>(
        wn_, Wv, ctx_, 512, 256, 256, nullptr, nullptr, nullptr);
    gemm_mma<0><<<dim3(256, 2), blk, GEMM_SMEM_BYTES>>>(
        wn_ + 256, Wv + 128 * 256, ctx_ + 128, 512, 256, 256,
        nullptr, nullptr, nullptr);
    // g2 = ctx @ W_gate[:, 256:]^T, fused gate epilogue -> out
    gemm_mma<1><<<dim3(256, 4), blk, GEMM_SMEM_BYTES>>>(
        ctx_, Wg + 256, g1_, 256, 512, 256, bg, center, out);
}

// round 4
// speedup vs baseline: 2.5277x; 1.3036x over previous
#include <cuda_runtime.h>
#include <math.h>
#include <stdint.h>

#define NB 32768

// ---------------- scratch (device globals: no allocation allowed) -------------
__device__ float g_q  [NB * 64];        // [B,64]   q = center @ Wq^T
__device__ float g_p  [NB * 512];       // [B,2,256] p[b,h] = q[b,h] @ Wk_h
__device__ float g_g1 [NB * 256];       // center part of gate pre-activation
__device__ float g_wn [NB * 512];       // [B,2,256] attention-weighted neighbor sum
__device__ float g_ctx[NB * 256];       // context

// =============================================================================
// tf32 helpers (legacy mma.sync path — compute_103 baseline, no 'a' features)
// =============================================================================
__device__ __forceinline__ uint32_t f2tf(float x) {
    uint32_t r;
    asm("cvt.rna.tf32.f32 %0, %1;" : "=r"(r) : "f"(x));
    return r;
}

__device__ __forceinline__ void mma_tf32(float* d, const uint32_t* a, const uint32_t* b) {
    asm volatile(
        "mma.sync.aligned.m16n8k8.row.col.f32.tf32.tf32.f32 "
        "{%0,%1,%2,%3}, {%4,%5,%6,%7}, {%8,%9}, {%0,%1,%2,%3};"
        : "+f"(d[0]), "+f"(d[1]), "+f"(d[2]), "+f"(d[3])
        : "r"(a[0]), "r"(a[1]), "r"(a[2]), "r"(a[3]), "r"(b[0]), "r"(b[1]));
}

// =============================================================================
// Tensor-core GEMM (mma.sync tf32):  C[m,n] = sum_k A[m,k] * W[n,k]   K=256
// CTA tile: BM=128, BN=64, BK=32. 8 warps as 4(m) x 2(n), warp tile 32x32.
// Smem k-major, strides 132/68 (conflict-free fragment reads). Double buffered.
// EPI=1: gated epilogue out = g*center + (1-g)*A, g = sigmoid(acc + C + bias)
// =============================================================================
#define AS_STR 132
#define WS_STR 68
#define AS_FLOATS (32 * AS_STR)      // 4224
#define WS_FLOATS (32 * WS_STR)      // 2176
#define GEMM_SMEM_BYTES ((2 * AS_FLOATS + 2 * WS_FLOATS) * 4)   // 51200

template <int EPI>
__global__ __launch_bounds__(256) void gemm_mma(
    const float* __restrict__ A, const float* __restrict__ W,
    float* __restrict__ C, int lda, int ldw, int ldc,
    const float* __restrict__ bias, const float* __restrict__ center,
    float* __restrict__ outp)
{
    extern __shared__ float ds[];
    float* Asb[2] = {ds, ds + AS_FLOATS};
    float* Wsb[2] = {ds + 2 * AS_FLOATS, ds + 2 * AS_FLOATS + WS_FLOATS};

    const int tid  = threadIdx.x;
    const int wid  = tid >> 5;
    const int lane = tid & 31;
    const int m0   = blockIdx.x * 128;
    const int n0   = blockIdx.y * 64;
    const int wm   = (wid & 3) * 32;
    const int wn   = (wid >> 2) * 32;

    float4 ra[4], rw[2];
    {
        const float* Ab = A + (size_t)m0 * lda;
        const float* Wb = W + (size_t)n0 * ldw;
#pragma unroll
        for (int i = 0; i < 4; i++) {
            const int idx = tid + 256 * i, r = idx >> 3, kq = idx & 7;
            ra[i] = *(const float4*)(Ab + (size_t)r * lda + kq * 4);
        }
#pragma unroll
        for (int i = 0; i < 2; i++) {
            const int idx = tid + 256 * i, r = idx >> 3, kq = idx & 7;
            rw[i] = *(const float4*)(Wb + (size_t)r * ldw + kq * 4);
        }
    }

    float acc[2][4][4];
#pragma unroll
    for (int i = 0; i < 2; i++)
#pragma unroll
        for (int j = 0; j < 4; j++)
#pragma unroll
            for (int v = 0; v < 4; v++) acc[i][j][v] = 0.f;

    {
        float* As = Asb[0];
        float* Ws = Wsb[0];
#pragma unroll
        for (int i = 0; i < 4; i++) {
            const int idx = tid + 256 * i, r = idx >> 3, kq = idx & 7;
            As[(kq * 4 + 0) * AS_STR + r] = __uint_as_float(f2tf(ra[i].x));
            As[(kq * 4 + 1) * AS_STR + r] = __uint_as_float(f2tf(ra[i].y));
            As[(kq * 4 + 2) * AS_STR + r] = __uint_as_float(f2tf(ra[i].z));
            As[(kq * 4 + 3) * AS_STR + r] = __uint_as_float(f2tf(ra[i].w));
        }
#pragma unroll
        for (int i = 0; i < 2; i++) {
            const int idx = tid + 256 * i, r = idx >> 3, kq = idx & 7;
            Ws[(kq * 4 + 0) * WS_STR + r] = __uint_as_float(f2tf(rw[i].x));
            Ws[(kq * 4 + 1) * WS_STR + r] = __uint_as_float(f2tf(rw[i].y));
            Ws[(kq * 4 + 2) * WS_STR + r] = __uint_as_float(f2tf(rw[i].z));
            Ws[(kq * 4 + 3) * WS_STR + r] = __uint_as_float(f2tf(rw[i].w));
        }
    }
    __syncthreads();

#pragma unroll 1
    for (int it = 0; it < 8; it++) {
        const int cur = it & 1;
        if (it < 7) {
            const int kb = (it + 1) * 32;
            const float* Ab = A + (size_t)m0 * lda + kb;
            const float* Wb = W + (size_t)n0 * ldw + kb;
#pragma unroll
            for (int i = 0; i < 4; i++) {
                const int idx = tid + 256 * i, r = idx >> 3, kq = idx & 7;
                ra[i] = *(const float4*)(Ab + (size_t)r * lda + kq * 4);
            }
#pragma unroll
            for (int i = 0; i < 2; i++) {
                const int idx = tid + 256 * i, r = idx >> 3, kq = idx & 7;
                rw[i] = *(const float4*)(Wb + (size_t)r * ldw + kq * 4);
            }
        }
        {
            const float* As = Asb[cur];
            const float* Ws = Wsb[cur];
#pragma unroll
            for (int ks = 0; ks < 4; ks++) {
                const int kk = ks * 8;
                uint32_t afr[2][4], bfr[4][2];
                const int c = lane & 3, r = lane >> 2;
#pragma unroll
                for (int i = 0; i < 2; i++) {
                    const int r0 = wm + i * 16 + r;
                    afr[i][0] = __float_as_uint(As[(kk + c) * AS_STR + r0]);
                    afr[i][1] = __float_as_uint(As[(kk + c) * AS_STR + r0 + 8]);
                    afr[i][2] = __float_as_uint(As[(kk + c + 4) * AS_STR + r0]);
                    afr[i][3] = __float_as_uint(As[(kk + c + 4) * AS_STR + r0 + 8]);
                }
#pragma unroll
                for (int j = 0; j < 4; j++) {
                    const int c0 = wn + j * 8 + r;
                    bfr[j][0] = __float_as_uint(Ws[(kk + c) * WS_STR + c0]);
                    bfr[j][1] = __float_as_uint(Ws[(kk + c + 4) * WS_STR + c0]);
                }
#pragma unroll
                for (int i = 0; i < 2; i++)
#pragma unroll
                    for (int j = 0; j < 4; j++)
                        mma_tf32(acc[i][j], afr[i], bfr[j]);
            }
        }
        if (it < 7) {
            const int nxt = 1 - cur;
            float* As = Asb[nxt];
            float* Ws = Wsb[nxt];
#pragma unroll
            for (int i = 0; i < 4; i++) {
                const int idx = tid + 256 * i, r = idx >> 3, kq = idx & 7;
                As[(kq * 4 + 0) * AS_STR + r] = __uint_as_float(f2tf(ra[i].x));
                As[(kq * 4 + 1) * AS_STR + r] = __uint_as_float(f2tf(ra[i].y));
                As[(kq * 4 + 2) * AS_STR + r] = __uint_as_float(f2tf(ra[i].z));
                As[(kq * 4 + 3) * AS_STR + r] = __uint_as_float(f2tf(ra[i].w));
            }
#pragma unroll
            for (int i = 0; i < 2; i++) {
                const int idx = tid + 256 * i, r = idx >> 3, kq = idx & 7;
                Ws[(kq * 4 + 0) * WS_STR + r] = __uint_as_float(f2tf(rw[i].x));
                Ws[(kq * 4 + 1) * WS_STR + r] = __uint_as_float(f2tf(rw[i].y));
                Ws[(kq * 4 + 2) * WS_STR + r] = __uint_as_float(f2tf(rw[i].z));
                Ws[(kq * 4 + 3) * WS_STR + r] = __uint_as_float(f2tf(rw[i].w));
            }
        }
        __syncthreads();
    }

    const int r = lane >> 2, c2 = (lane & 3) * 2;
#pragma unroll
    for (int i = 0; i < 2; i++) {
#pragma unroll
        for (int j = 0; j < 4; j++) {
            const int row0 = m0 + wm + i * 16 + r;
            const int col  = n0 + wn + j * 8 + c2;
#pragma unroll
            for (int half = 0; half < 2; half++) {
                const int row = row0 + half * 8;
                const float d0 = acc[i][j][2 * half + 0];
                const float d1 = acc[i][j][2 * half + 1];
                if (EPI == 0) {
                    *(float2*)(C + (size_t)row * ldc + col) = make_float2(d0, d1);
                } else {
                    const float2 g1v = *(const float2*)(C      + (size_t)row * 256 + col);
                    const float2 bv  = *(const float2*)(bias   + col);
                    const float2 cv  = *(const float2*)(center + (size_t)row * 256 + col);
                    const float2 xv  = *(const float2*)(A      + (size_t)row * lda + col);
                    float z0 = d0 + g1v.x + bv.x;
                    float z1 = d1 + g1v.y + bv.y;
                    const float gg0 = 1.f / (1.f + __expf(-z0));
                    const float gg1 = 1.f / (1.f + __expf(-z1));
                    float2 o;
                    o.x = gg0 * cv.x + (1.f - gg0) * xv.x;
                    o.y = gg1 * cv.y + (1.f - gg1) * xv.y;
                    *(float2*)(outp + (size_t)row * 256 + col) = o;
                }
            }
        }
    }
}

// =============================================================================
// p kernel:  p[b,h,d] = sum_{a<32} q[b, h*32+a] * Wk[h*32+a, d]
// =============================================================================
__global__ __launch_bounds__(256) void p_kernel(const float* __restrict__ Wk)
{
    __shared__ float qs[64 * 64];
    const int t = threadIdx.x;              // t == d
    float wk[64];
#pragma unroll
    for (int r = 0; r < 64; r++) wk[r] = Wk[r * 256 + t];

    const int b0 = blockIdx.x * 64;
    const float4* qsrc = (const float4*)(g_q + (size_t)b0 * 64);
    for (int i = t; i < 1024; i += 256) ((float4*)qs)[i] = qsrc[i];
    __syncthreads();

#pragma unroll 1
    for (int bb = 0; bb < 64; bb++) {
        float p0 = 0.f, p1 = 0.f;
#pragma unroll
        for (int a4 = 0; a4 < 8; a4++) {
            const float4 q0 = *(const float4*)&qs[bb * 64 + a4 * 4];
            const float4 q1 = *(const float4*)&qs[bb * 64 + 32 + a4 * 4];
            p0 = fmaf(q0.x, wk[a4 * 4 + 0], p0);
            p0 = fmaf(q0.y, wk[a4 * 4 + 1], p0);
            p0 = fmaf(q0.z, wk[a4 * 4 + 2], p0);
            p0 = fmaf(q0.w, wk[a4 * 4 + 3], p0);
            p1 = fmaf(q1.x, wk[32 + a4 * 4 + 0], p1);
            p1 = fmaf(q1.y, wk[32 + a4 * 4 + 1], p1);
            p1 = fmaf(q1.z, wk[32 + a4 * 4 + 2], p1);
            p1 = fmaf(q1.w, wk[32 + a4 * 4 + 3], p1);
        }
        const size_t o = (size_t)(b0 + bb) * 512;
        g_p[o + t]       = p0;
        g_p[o + 256 + t] = p1;
    }
}

// =============================================================================
// Register-resident attention: one CTA per b, 256 threads = 8 warps.
// Thread (w,lane) owns 8 neighbor rows (k = it*8+w) x 8 dims
// (4*lane..4*lane+3 and 128+4*lane..): the CTA's whole 64x256 tile lives in
// registers. All 16 LDG.128/thread issued up front (deep MLP), scores via
// full-warp shfl reduce, ONE barrier, plain softmax over K=64, ONE barrier,
// weighted sum from registers, 16KB smem cross-warp reduce. neigh read once.
// =============================================================================
__global__ __launch_bounds__(256) void attn_reg(
    const float* __restrict__ neigh, const float* __restrict__ wts)
{
    __shared__ float sAcc[8][512];        // 16 KB cross-warp reduction
    __shared__ float sScore[2][64];
    __shared__ float sAttn[2][64];
    __shared__ float sWt[64];

    const int b    = blockIdx.x;
    const int t    = threadIdx.x;
    const int w    = t >> 5;
    const int lane = t & 31;

    if (t < 64) sWt[t] = wts[(size_t)b * 64 + t] * 0.17677669529663687f; // /sqrt(32)

    const float4* pp = (const float4*)(g_p + (size_t)b * 512);
    const float4 p0a = pp[lane];
    const float4 p0b = pp[32 + lane];
    const float4 p1a = pp[64 + lane];
    const float4 p1b = pp[96 + lane];

    const float* nbp = neigh + (size_t)b * 64 * 256;

    float4 va[8], vb[8];
#pragma unroll
    for (int it = 0; it < 8; it++) {            // front-batched: 16 LDG.128
        const int k = it * 8 + w;
        va[it] = *(const float4*)(nbp + k * 256 + 4 * lane);
        vb[it] = *(const float4*)(nbp + k * 256 + 128 + 4 * lane);
    }

#pragma unroll
    for (int it = 0; it < 8; it++) {
        float s0 = va[it].x * p0a.x + va[it].y * p0a.y + va[it].z * p0a.z + va[it].w * p0a.w
                 + vb[it].x * p0b.x + vb[it].y * p0b.y + vb[it].z * p0b.z + vb[it].w * p0b.w;
        float s1 = va[it].x * p1a.x + va[it].y * p1a.y + va[it].z * p1a.z + va[it].w * p1a.w
                 + vb[it].x * p1b.x + vb[it].y * p1b.y + vb[it].z * p1b.z + vb[it].w * p1b.w;
#pragma unroll
        for (int o = 16; o; o >>= 1) {
            s0 += __shfl_xor_sync(0xffffffffu, s0, o);
            s1 += __shfl_xor_sync(0xffffffffu, s1, o);
        }
        if (lane == 0) {
            sScore[0][it * 8 + w] = s0;
            sScore[1][it * 8 + w] = s1;
        }
    }
    __syncthreads();

    if (t < 64) {                    // warps 0,1: one head each
        const int h = t >> 5, l = t & 31;
        const float sa = sScore[h][l]      * sWt[l];
        const float sb = sScore[h][32 + l] * sWt[32 + l];
        float mx = fmaxf(sa, sb);
#pragma unroll
        for (int o = 16; o; o >>= 1) mx = fmaxf(mx, __shfl_xor_sync(0xffffffffu, mx, o));
        const float ea = __expf(sa - mx), eb = __expf(sb - mx);
        float sum = ea + eb;
#pragma unroll
        for (int o = 16; o; o >>= 1) sum += __shfl_xor_sync(0xffffffffu, sum, o);
        const float inv = 1.f / sum;
        sAttn[h][l]      = ea * inv;
        sAttn[h][32 + l] = eb * inv;
    }
    __syncthreads();

    float4 a0a = {0,0,0,0}, a0b = {0,0,0,0}, a1a = {0,0,0,0}, a1b = {0,0,0,0};
#pragma unroll
    for (int it = 0; it < 8; it++) {
        const float w0 = sAttn[0][it * 8 + w];   // warp-uniform broadcast
        const float w1 = sAttn[1][it * 8 + w];
        a0a.x = fmaf(w0, va[it].x, a0a.x);  a0a.y = fmaf(w0, va[it].y, a0a.y);
        a0a.z = fmaf(w0, va[it].z, a0a.z);  a0a.w = fmaf(w0, va[it].w, a0a.w);
        a0b.x = fmaf(w0, vb[it].x, a0b.x);  a0b.y = fmaf(w0, vb[it].y, a0b.y);
        a0b.z = fmaf(w0, vb[it].z, a0b.z);  a0b.w = fmaf(w0, vb[it].w, a0b.w);
        a1a.x = fmaf(w1, va[it].x, a1a.x);  a1a.y = fmaf(w1, va[it].y, a1a.y);
        a1a.z = fmaf(w1, va[it].z, a1a.z);  a1a.w = fmaf(w1, va[it].w, a1a.w);
        a1b.x = fmaf(w1, vb[it].x, a1b.x);  a1b.y = fmaf(w1, vb[it].y, a1b.y);
        a1b.z = fmaf(w1, vb[it].z, a1b.z);  a1b.w = fmaf(w1, vb[it].w, a1b.w);
    }

    float4* row = (float4*)&sAcc[w][0];
    row[lane]      = a0a;
    row[32 + lane] = a0b;
    row[64 + lane] = a1a;
    row[96 + lane] = a1b;
    __syncthreads();

    float s_lo = 0.f, s_hi = 0.f;
#pragma unroll
    for (int ww = 0; ww < 8; ww++) {
        s_lo += sAcc[ww][t];
        s_hi += sAcc[ww][t + 256];
    }
    g_wn[(size_t)b * 512 + t]       = s_lo;
    g_wn[(size_t)b * 512 + 256 + t] = s_hi;
}

// =============================================================================
extern "C" void kernel_launch(void* const* d_in, const int* in_sizes, int n_in,
                              void* d_out, int out_size)
{
    const float* center = (const float*)d_in[0];
    const float* neigh  = (const float*)d_in[1];
    const float* wts    = (const float*)d_in[2];
    const float* Wq     = (const float*)d_in[3];
    const float* Wk     = (const float*)d_in[4];
    const float* Wv     = (const float*)d_in[5];
    const float* Wg     = (const float*)d_in[6];
    const float* bg     = (const float*)d_in[7];
    float* out = (float*)d_out;

    float *q_, *g1_, *wn_, *ctx_;
    cudaGetSymbolAddress((void**)&q_,   g_q);
    cudaGetSymbolAddress((void**)&g1_,  g_g1);
    cudaGetSymbolAddress((void**)&wn_,  g_wn);
    cudaGetSymbolAddress((void**)&ctx_, g_ctx);

    cudaFuncSetAttribute(gemm_mma<0>,
                         cudaFuncAttributeMaxDynamicSharedMemorySize, GEMM_SMEM_BYTES);
    cudaFuncSetAttribute(gemm_mma<1>,
                         cudaFuncAttributeMaxDynamicSharedMemorySize, GEMM_SMEM_BYTES);

    const dim3 blk(256);

    // q = center @ Wq^T                       [B,64]
    gemm_mma<0><<<dim3(256, 1), blk, GEMM_SMEM_BYTES>>>(
        center, Wq, q_, 256, 256, 64, nullptr, nullptr, nullptr);
    // g1 = center @ W_gate[:, :256]^T         [B,256]
    gemm_mma<0><<<dim3(256, 4), blk, GEMM_SMEM_BYTES>>>(
        center, Wg, g1_, 256, 512, 256, nullptr, nullptr, nullptr);
    // p[b,h] = q[b,h] @ Wk_h                  [B,2,256]
    p_kernel<<<512, blk>>>(Wk);
    // attention -> wn                         [B,2,256]
    attn_reg<<<NB, blk>>>(neigh, wts);
    // context_h = wn_h @ Wv_h^T               [B,256] (block-diagonal over heads)
    gemm_mma<0><<<dim3(256, 2), blk, GEMM_SMEM_BYTES>>>(
        wn_, Wv, ctx_, 512, 256, 256, nullptr, nullptr, nullptr);
    gemm_mma<0><<<dim3(256, 2), blk, GEMM_SMEM_BYTES>>>(
        wn_ + 256, Wv + 128 * 256, ctx_ + 128, 512, 256, 256,
        nullptr, nullptr, nullptr);
    // g2 = ctx @ W_gate[:, 256:]^T, fused gate epilogue -> out
    gemm_mma<1><<<dim3(256, 4), blk, GEMM_SMEM_BYTES>>>(
        ctx_, Wg + 256, g1_, 256, 512, 256, bg, center, out);
}